// round 6
// baseline (speedup 1.0000x reference)
#include <cuda_runtime.h>

#define LW 512
#define LH 512
#define NIMG 12
#define RAD 8
#define HW 2048

// Low-res {A, b} interleaved — only intermediate that touches HBM (24 MB).
__device__ float2 g_AB[(size_t)NIMG * LH * LW];

// ---------------------------------------------------------------------------
// Kernel 1 (fused stats) — round-4 version, known good (~30us).
// Tile = 64 out-cols x 16 out-rows. Grid = 8 x 32 x 12 = 3072 blocks, 128 thr.
// ---------------------------------------------------------------------------
#define TC 64                 // out cols per tile
#define TR 16                 // out rows per tile
#define VC (TC + 2 * RAD)     // 80 loaded cols
#define VW 89                 // padded V row width (vpad(79)=88 -> 89)
#define STH 128

__device__ __forceinline__ int vpad(int v) { return v + (v >> 3); }

__global__ __launch_bounds__(STH) void stats_kernel(const float* __restrict__ lrx,
                                                    const float* __restrict__ lry) {
    __shared__ float4 Vsh[TR][VW];              // 22.8 KB vertical window sums
    __shared__ float2 ABsh[TR][TC];             // 8 KB
    __shared__ float2 ring[2 * RAD + 1][VC];    // 10.9 KB raw-row ring {x,y}

    int img = blockIdx.z;
    int cb  = blockIdx.x * TC;
    int r0  = blockIdx.y * TR;
    int t   = threadIdx.x;

    const float* xim = lrx + (size_t)img * LH * LW;
    const float* yim = lry + (size_t)img * LH * LW;

    // ---------------- phase 1: vertical sliding windows -------------------
    if (t < VC) {
        int gcol = cb - RAD + t;                // may be <0 or >=LW at edges
        bool cok = (gcol >= 0 && gcol < LW);
        float sx = 0.f, sy = 0.f, sxy = 0.f, sxx = 0.f;

        // init: rows r0-8 .. r0+8 (rows <0 contribute zero; r0+8 < LH always)
        for (int rr = r0 - RAD; rr <= r0 + RAD; ++rr) {
            float xv = 0.f, yv = 0.f;
            if (cok && rr >= 0) {
                xv = __ldg(xim + (size_t)rr * LW + gcol);
                yv = __ldg(yim + (size_t)rr * LW + gcol);
            }
            ring[(rr + 17) % 17][t] = make_float2(xv, yv);
            sx += xv; sy += yv; sxy += xv * yv; sxx += xv * xv;
        }

        for (int i = 0; i < TR; ++i) {
            Vsh[i][vpad(t)] = make_float4(sx, sy, sxy, sxx);

            int rsub = r0 + i - RAD;
            int radd = r0 + i + RAD + 1;        // radd - rsub = 17: same slot
            if (rsub >= 0) {
                float2 o = ring[(rsub + 17) % 17][t];  // read old FIRST
                sx -= o.x; sy -= o.y; sxy -= o.x * o.y; sxx -= o.x * o.x;
            }
            float xv = 0.f, yv = 0.f;
            if (cok && radd < LH) {
                xv = __ldg(xim + (size_t)radd * LW + gcol);
                yv = __ldg(yim + (size_t)radd * LW + gcol);
            }
            ring[radd % 17][t] = make_float2(xv, yv);
            sx += xv; sy += yv; sxy += xv * yv; sxx += xv * xv;
        }
    }
    __syncthreads();

    // ---------------- phase 2: horizontal sliding + A,b -------------------
    {
        int i   = t >> 3;          // row in tile, 0..15
        int seg = t & 7;           // 8-px segment, 0..7
        int c0  = seg * 8;
        int r   = r0 + i;

        int ylo = r - RAD; if (ylo < 0) ylo = 0;
        int yhi = r + RAD; if (yhi > LH - 1) yhi = LH - 1;
        float ny = (float)(yhi - ylo + 1);

        float sx = 0.f, sy = 0.f, sxy = 0.f, sxx = 0.f;
#pragma unroll
        for (int v = c0; v <= c0 + 2 * RAD; ++v) {
            float4 w = Vsh[i][vpad(v)];
            sx += w.x; sy += w.y; sxy += w.z; sxx += w.w;
        }
#pragma unroll
        for (int k = 0; k < 8; ++k) {
            int c  = c0 + k;
            int gc = cb + c;
            int xlo = gc - RAD; if (xlo < 0) xlo = 0;
            int xhi = gc + RAD; if (xhi > LW - 1) xhi = LW - 1;
            float invN = 1.0f / ((float)(xhi - xlo + 1) * ny);

            float mx  = sx  * invN;
            float my  = sy  * invN;
            float cov = sxy * invN - mx * my;
            float var = sxx * invN - mx * mx;
            float A   = cov / (var + 1e-8f);
            ABsh[i][c] = make_float2(A, my - A * mx);

            if (k < 7) {
                float4 a = Vsh[i][vpad(c + 2 * RAD + 1)];
                float4 s = Vsh[i][vpad(c)];
                sx += a.x - s.x; sy += a.y - s.y;
                sxy += a.z - s.z; sxx += a.w - s.w;
            }
        }
    }
    __syncthreads();

    // ---------------- coalesced output write ------------------------------
    size_t abase = (size_t)img * LH * LW;
    for (int idx = t; idx < TR * TC; idx += STH) {
        int i = idx >> 6;
        int c = idx & 63;
        g_AB[abase + (size_t)(r0 + i) * LW + cb + c] = ABsh[i][c];
    }
}

// ---------------------------------------------------------------------------
// Kernel 2: fused bilinear upsample. One block = one output row; one thread
// = 8 consecutive pixels. 8 px span <2 low-res cells -> preload 4 float2
// from shared, per-pixel predicated selection (4B of LDS per pixel).
// ---------------------------------------------------------------------------
#define UPTHREADS 256

__global__ __launch_bounds__(UPTHREADS) void upsample_kernel(
        const float* __restrict__ hrx, float* __restrict__ out) {
    int bid = blockIdx.x;
    int oy  = bid & 2047;
    int img = bid >> 11;
    int t   = threadIdx.x;

    const float SC = 511.0f / 2047.0f;

    float yf = (float)oy * SC;
    int y0 = (int)yf; if (y0 > LH - 1) y0 = LH - 1;
    int y1 = y0 + 1;  if (y1 > LH - 1) y1 = LH - 1;
    float wy = yf - (float)y0;

    const float2* AB0 = g_AB + ((size_t)img * LH + y0) * LW;
    const float2* AB1 = g_AB + ((size_t)img * LH + y1) * LW;

    __shared__ float2 sAB[LW];   // y-interpolated {A,b} for the whole row

#pragma unroll
    for (int i = 0; i < 2; ++i) {
        int xc = t + i * UPTHREADS;
        float2 v0 = __ldg(AB0 + xc);
        float2 v1 = __ldg(AB1 + xc);
        sAB[xc] = make_float2(v0.x + wy * (v1.x - v0.x),
                              v0.y + wy * (v1.y - v0.y));
    }
    __syncthreads();

    int ox0  = t * 8;
    float xf0 = (float)ox0 * SC;
    int xb = (int)xf0;
    if (xb < 0) xb = 0;
    if (xb > LW - 3) xb = LW - 3;            // defensive: keep xb..xb+2 valid
    float fb = (float)xb;

    int i1 = xb + 1;
    int i2 = xb + 2;
    int i3 = xb + 3; if (i3 > LW - 1) i3 = LW - 1;
    float2 p0 = sAB[xb];
    float2 p1 = sAB[i1];
    float2 p2 = sAB[i2];
    float2 p3 = sAB[i3];

    size_t off = ((size_t)img * HW + oy) * HW + ox0;
    float4 h0 = __ldcs(reinterpret_cast<const float4*>(hrx + off));
    float4 h1 = __ldcs(reinterpret_cast<const float4*>(hrx + off + 4));
    float hv[8] = {h0.x, h0.y, h0.z, h0.w, h1.x, h1.y, h1.z, h1.w};
    float res[8];

#pragma unroll
    for (int k = 0; k < 8; ++k) {
        float frac = fmaf((float)(ox0 + k), SC, -fb);   // in [0, 3)
        bool b1 = frac >= 1.0f;
        bool b2 = frac >= 2.0f;
        float wx = frac - (b1 ? 1.0f : 0.0f) - (b2 ? 1.0f : 0.0f);

        float paA = p0.x, paB = p0.y, pbA = p1.x, pbB = p1.y;
        if (b1) { paA = p1.x; paB = p1.y; pbA = p2.x; pbB = p2.y; }
        if (b2) { paA = p2.x; paB = p2.y; pbA = p3.x; pbB = p3.y; }

        float Av = paA + wx * (pbA - paA);
        float Bv = paB + wx * (pbB - paB);
        res[k] = Av * hv[k] + Bv;
    }

    __stcs(reinterpret_cast<float4*>(out + off),
           make_float4(res[0], res[1], res[2], res[3]));
    __stcs(reinterpret_cast<float4*>(out + off + 4),
           make_float4(res[4], res[5], res[6], res[7]));
}

// ---------------------------------------------------------------------------
extern "C" void kernel_launch(void* const* d_in, const int* in_sizes, int n_in,
                              void* d_out, int out_size) {
    const float* lrx = (const float*)d_in[0];
    const float* lry = (const float*)d_in[1];
    const float* hrx = (const float*)d_in[2];
    float* out = (float*)d_out;

    dim3 sgrid(LW / TC, LH / TR, NIMG);      // 8 x 32 x 12 = 3072 blocks
    stats_kernel<<<sgrid, STH>>>(lrx, lry);

    upsample_kernel<<<NIMG * HW, UPTHREADS>>>(hrx, out);
}